// round 2
// baseline (speedup 1.0000x reference)
#include <cuda_runtime.h>

// Fused: avgpool(5x5,s2) + Linear(36->1) == per-(b,c) dot of the 256-elem row
// with a folded 16x16 filter G, where
//   G[h*16+w] = (1/25) * sum_{windows (i,j) covering (h,w)} W[i*6+j].
// Each block rebuilds G in shared memory from W (cheap: 36 L2-resident floats).
// Each warp handles ROWS_PER_WARP=4 contiguous rows with 8 front-batched
// float4 loads per lane for high MLP.

#define ROWS_PER_WARP 4

__global__ void __launch_bounds__(256)
pool_linear_kernel(const float4* __restrict__ x,
                   const float* __restrict__ W,
                   const float* __restrict__ bias,
                   float* __restrict__ out) {
    __shared__ float gsh[256];
    __shared__ float bsh;

    int tid = threadIdx.x;

    // Build folded filter G into shared (each thread computes one of 256 taps).
    {
        int h = tid >> 4;
        int w = tid & 15;
        float s = 0.0f;
        #pragma unroll
        for (int i = 0; i < 6; i++) {
            int top = i * 2;
            bool hin = (h >= top) && (h <= top + 4);
            #pragma unroll
            for (int j = 0; j < 6; j++) {
                int left = j * 2;
                if (hin && (w >= left) && (w <= left + 4)) s += W[i * 6 + j];
            }
        }
        gsh[tid] = s * 0.04f;   // 1/25
        if (tid == 0) bsh = bias[0];
    }
    __syncthreads();

    int lane = tid & 31;
    int warp_in_blk = tid >> 5;                       // 0..7
    int gwarp = blockIdx.x * 8 + warp_in_blk;
    int row_base = gwarp * ROWS_PER_WARP;             // first of 4 rows

    // Load filter into registers (two float4 per lane covering row layout).
    const float4* gv = reinterpret_cast<const float4*>(gsh);
    float4 g0 = gv[lane];
    float4 g1 = gv[lane + 32];

    // Front-batched loads: 8 independent float4 (2 per row x 4 rows).
    const float4* p = x + (size_t)row_base * 64;
    float4 a[ROWS_PER_WARP], b[ROWS_PER_WARP];
    #pragma unroll
    for (int r = 0; r < ROWS_PER_WARP; r++) {
        a[r] = p[r * 64 + lane];
        b[r] = p[r * 64 + lane + 32];
    }

    float s[ROWS_PER_WARP];
    #pragma unroll
    for (int r = 0; r < ROWS_PER_WARP; r++) {
        s[r] = a[r].x * g0.x + a[r].y * g0.y + a[r].z * g0.z + a[r].w * g0.w
             + b[r].x * g1.x + b[r].y * g1.y + b[r].z * g1.z + b[r].w * g1.w;
    }

    // Butterfly reductions (4 independent chains interleave well).
    #pragma unroll
    for (int off = 16; off > 0; off >>= 1) {
        #pragma unroll
        for (int r = 0; r < ROWS_PER_WARP; r++)
            s[r] += __shfl_xor_sync(0xffffffffu, s[r], off);
    }

    if (lane < ROWS_PER_WARP)
        out[row_base + lane] = s[lane] + bsh;
}

extern "C" void kernel_launch(void* const* d_in, const int* in_sizes, int n_in,
                              void* d_out, int out_size) {
    const float* x = (const float*)d_in[0];   // [256, 512, 16, 16]
    const float* W = (const float*)d_in[1];   // [1, 36]
    const float* b = (const float*)d_in[2];   // [1]
    float* out = (float*)d_out;               // [256*512]

    int n_rows = out_size;                    // 131072
    int warps = n_rows / ROWS_PER_WARP;       // 32768
    int blocks = warps / 8;                   // 4096 (8 warps per 256-thr block)

    pool_linear_kernel<<<blocks, 256>>>(
        reinterpret_cast<const float4*>(x), W, b, out);
}

// round 4
// speedup vs baseline: 1.0701x; 1.0701x over previous
#include <cuda_runtime.h>

// Fused avgpool(5x5,s2) + Linear(36->1): per-(b,c) dot of 256-elem row with a
// folded 16x16 filter G, G[h*16+w] = (1/25)*sum_{windows covering (h,w)} W[i*6+j].
//
// Warp layout: 4 contiguous rows per warp; lane = (rsub<<3)|chunk,
// rsub = row within warp (0..3), chunk = 32-float segment (0..7).
// Each lane: 8 front-batched float4 loads -> dot vs filter -> 3-level
// shfl_xor reduce within 8-lane groups -> lanes chunk==0 store.
//
// Filter built per-block in smem AFTER the x loads are issued, so its
// ~300-cycle build overlaps the DRAM load latency.

__global__ void __launch_bounds__(256)
pool_linear_kernel(const float4* __restrict__ x,
                   const float* __restrict__ W,
                   const float* __restrict__ bias,
                   float* __restrict__ out) {
    int tid   = threadIdx.x;
    int lane  = tid & 31;
    int warp  = tid >> 5;                       // 0..7
    int chunk = lane & 7;                       // 32-float segment
    int rsub  = lane >> 3;                      // row within warp

    int gwarp    = blockIdx.x * 8 + warp;
    int row_base = gwarp * 4;

    // ---- Front-batch 8 independent float4 loads (issued before anything else)
    const float4* p = x + (size_t)(row_base + rsub) * 64 + chunk;
    float4 a[8];
    #pragma unroll
    for (int k = 0; k < 8; k++)
        a[k] = p[k * 8];

    // ---- Build folded filter in shared (overlaps the loads above)
    __shared__ float gsh[256];
    __shared__ float bsh;
    {
        int h = tid >> 4;
        int w = tid & 15;
        float s = 0.0f;
        #pragma unroll
        for (int i = 0; i < 6; i++) {
            int top = i * 2;
            bool hin = (h >= top) && (h <= top + 4);
            #pragma unroll
            for (int j = 0; j < 6; j++) {
                int left = j * 2;
                if (hin && (w >= left) && (w <= left + 4)) s += W[i * 6 + j];
            }
        }
        gsh[tid] = s * 0.04f;                   // 1/25
        if (tid == 0) bsh = bias[0];
    }
    __syncthreads();

    // ---- Dot product: lane covers filter float4 indices chunk + 8k
    const float4* gv = reinterpret_cast<const float4*>(gsh);
    float s0 = 0.0f, s1 = 0.0f;
    #pragma unroll
    for (int k = 0; k < 8; k += 2) {
        float4 g0 = gv[k * 8 + chunk];
        float4 g1 = gv[(k + 1) * 8 + chunk];
        s0 += a[k].x * g0.x + a[k].y * g0.y + a[k].z * g0.z + a[k].w * g0.w;
        s1 += a[k + 1].x * g1.x + a[k + 1].y * g1.y + a[k + 1].z * g1.z + a[k + 1].w * g1.w;
    }
    float s = s0 + s1;

    // ---- Reduce within 8-lane groups (3 shuffles total, all rows in parallel)
    s += __shfl_xor_sync(0xffffffffu, s, 1);
    s += __shfl_xor_sync(0xffffffffu, s, 2);
    s += __shfl_xor_sync(0xffffffffu, s, 4);

    if (chunk == 0)
        out[row_base + rsub] = s + bsh;
}

extern "C" void kernel_launch(void* const* d_in, const int* in_sizes, int n_in,
                              void* d_out, int out_size) {
    const float* x = (const float*)d_in[0];   // [256, 512, 16, 16]
    const float* W = (const float*)d_in[1];   // [1, 36]
    const float* b = (const float*)d_in[2];   // [1]
    float* out = (float*)d_out;               // [256*512]

    int n_rows = out_size;                    // 131072
    int blocks = n_rows / 32;                 // 4 rows/warp * 8 warps = 32 rows/block

    pool_linear_kernel<<<blocks, 256>>>(
        reinterpret_cast<const float4*>(x), W, b, out);
}